// round 8
// baseline (speedup 1.0000x reference)
#include <cuda_runtime.h>
#include <cstdint>

#define Bb   8
#define Nn   1024
#define Cc   512
#define Kk   20
#define Mm   64
#define Pp   (Bb * Nn)        // 8192 points
#define CNT1 (Pp * Kk)        // 163840 samples for BN1
#define CNT2 Pp               // 8192 samples for BN2
#define EPS  1e-5f

// Scratch (no cudaMalloc allowed)
__device__ float g_W1hi[128 * 512];     // tf32-hi of folded W1'
__device__ float g_W1lo[128 * 512];     // tf32-lo of folded W1'
__device__ float g_y[Pp * 128];         // per-point y1(0:64) | y2(64:128)
__device__ float g_hmax[Pp * 64];
__device__ float g_hmin[Pp * 64];
__device__ float g_part1[128 * 256];    // transposed: [col(sum64|sq64)][block 256]
__device__ float g_bn1[128];            // scale(64) | bias(64)
__device__ float g_p2s[512 * 128];      // transposed: [col][ptile 128]
__device__ float g_p2q[512 * 128];
__device__ float g_bn2[1024];           // scale(512) | bias(512)
__device__ int   g_cntB = 0;
__device__ int   g_cntC = 0;
__device__ int   g_cntD = 0;
__device__ int   g_flagC = 0;

__device__ __forceinline__ float tf32_rna(float v) {
    uint32_t u;
    asm("cvt.rna.tf32.f32 %0, %1;" : "=r"(u) : "f"(v));
    return __uint_as_float(u);
}

__device__ __forceinline__ void mma_tf32(float* d, const float* a, const float* b) {
    asm volatile(
        "mma.sync.aligned.m16n8k8.row.col.f32.tf32.tf32.f32 "
        "{%0,%1,%2,%3}, {%4,%5,%6,%7}, {%8,%9}, {%0,%1,%2,%3};"
        : "+f"(d[0]), "+f"(d[1]), "+f"(d[2]), "+f"(d[3])
        : "r"(__float_as_uint(a[0])), "r"(__float_as_uint(a[1])),
          "r"(__float_as_uint(a[2])), "r"(__float_as_uint(a[3])),
          "r"(__float_as_uint(b[0])), "r"(__float_as_uint(b[1])));
}

__device__ __forceinline__ void tf32_split(float v, float& hi, float& lo) {
    hi = tf32_rna(v);
    lo = tf32_rna(v - hi);
}

// ---------------------------------------------------------------------------
// k0: fold W1 [64][1024] -> W1' [128][512], pre-split into tf32 hi/lo
// ---------------------------------------------------------------------------
__global__ void k0_prepw(const float* __restrict__ W1) {
    int i = blockIdx.x * 256 + threadIdx.x;      // 0..65535
    int n = i >> 9, c = i & 511;
    float v;
    if (n < 64) {
        v = W1[n * 1024 + c];
    } else {
        int m = n - 64;
        v = W1[m * 1024 + 512 + c] - W1[m * 1024 + c];
    }
    float hi = tf32_rna(v);
    g_W1hi[i] = hi;
    g_W1lo[i] = tf32_rna(v - hi);
}

// ---------------------------------------------------------------------------
// kA: GEMM1 y[8192][128] = x @ W1'^T, tf32 3-MMA, pre-split operands.
// Tile 32p x 128n, BK=16, 256 thr (8 warps: 2m x 4n, each m16 x n32),
// grid=256, 2 blocks/SM. Inner loop is pure LDS+MMA (no cvt).
// ---------------------------------------------------------------------------
__global__ void __launch_bounds__(256, 2) kA_gemm1(const float* __restrict__ x) {
    __shared__ float sxh[32][20], sxl[32][20];
    __shared__ float swh[128][20], swl[128][20];

    int tid = threadIdx.x;
    int lane = tid & 31, w = tid >> 5;
    int grp = lane >> 2, tig = lane & 3;
    int m_base = (w >> 2) * 16;     // 0 or 16
    int n_base = (w & 3) * 32;      // 0,32,64,96
    int p0 = blockIdx.x * 32;

    // x loader mapping: 32 rows x 16 cols, float2 per thread
    int xrow = tid >> 3;            // 0..31
    int xcol = (tid & 7) * 2;       // 0,2,..,14
    // W loader mapping: 128 rows x 16 cols, 8 floats per thread per array
    int wrow = tid >> 1;            // 0..127
    int wseg = (tid & 1) * 8;       // 0 or 8

    float acc[4][4];
#pragma unroll
    for (int j = 0; j < 4; j++)
#pragma unroll
        for (int q = 0; q < 4; q++) acc[j][q] = 0.f;

    for (int t = 0; t < 32; t++) {
        int k0 = t * 16;
        // x tile: load float2, split, store
        {
            float2 v = *reinterpret_cast<const float2*>(&x[(p0 + xrow) * 512 + k0 + xcol]);
            float h0, l0, h1, l1;
            tf32_split(v.x, h0, l0);
            tf32_split(v.y, h1, l1);
            *reinterpret_cast<float2*>(&sxh[xrow][xcol]) = make_float2(h0, h1);
            *reinterpret_cast<float2*>(&sxl[xrow][xcol]) = make_float2(l0, l1);
        }
        // W tiles: pre-split, straight copies
        {
            *reinterpret_cast<float4*>(&swh[wrow][wseg]) =
                *reinterpret_cast<const float4*>(&g_W1hi[wrow * 512 + k0 + wseg]);
            *reinterpret_cast<float4*>(&swh[wrow][wseg + 4]) =
                *reinterpret_cast<const float4*>(&g_W1hi[wrow * 512 + k0 + wseg + 4]);
            *reinterpret_cast<float4*>(&swl[wrow][wseg]) =
                *reinterpret_cast<const float4*>(&g_W1lo[wrow * 512 + k0 + wseg]);
            *reinterpret_cast<float4*>(&swl[wrow][wseg + 4]) =
                *reinterpret_cast<const float4*>(&g_W1lo[wrow * 512 + k0 + wseg + 4]);
        }
        __syncthreads();

#pragma unroll
        for (int ks = 0; ks < 16; ks += 8) {
            float ah[4], al[4], bh[4][2], bl[4][2];
            ah[0] = sxh[m_base + grp][ks + tig];
            ah[1] = sxh[m_base + grp + 8][ks + tig];
            ah[2] = sxh[m_base + grp][ks + tig + 4];
            ah[3] = sxh[m_base + grp + 8][ks + tig + 4];
            al[0] = sxl[m_base + grp][ks + tig];
            al[1] = sxl[m_base + grp + 8][ks + tig];
            al[2] = sxl[m_base + grp][ks + tig + 4];
            al[3] = sxl[m_base + grp + 8][ks + tig + 4];
#pragma unroll
            for (int j = 0; j < 4; j++) {
                int nc = n_base + j * 8 + grp;
                bh[j][0] = swh[nc][ks + tig];
                bh[j][1] = swh[nc][ks + tig + 4];
                bl[j][0] = swl[nc][ks + tig];
                bl[j][1] = swl[nc][ks + tig + 4];
            }
#pragma unroll
            for (int j = 0; j < 4; j++) {
                mma_tf32(acc[j], ah, bh[j]);
                mma_tf32(acc[j], al, bh[j]);
                mma_tf32(acc[j], ah, bl[j]);
            }
        }
        __syncthreads();
    }

    // epilogue: rows p0+m_base+grp (+8), cols n_base + j*8 + 2*tig
    {
        int prow = p0 + m_base + grp;
#pragma unroll
        for (int j = 0; j < 4; j++) {
            int col = n_base + j * 8 + 2 * tig;
            *reinterpret_cast<float2*>(&g_y[prow * 128 + col]) =
                make_float2(acc[j][0], acc[j][1]);
            *reinterpret_cast<float2*>(&g_y[(prow + 8) * 128 + col]) =
                make_float2(acc[j][2], acc[j][3]);
        }
    }
}

// ---------------------------------------------------------------------------
// kB: gather (max/min + sum/sumsq) + last-block BN1 finalize. grid=256, 256thr
// ---------------------------------------------------------------------------
__global__ void __launch_bounds__(256) kB_gather(const int* __restrict__ idx,
                                                 const float* __restrict__ gamma1,
                                                 const float* __restrict__ beta1) {
    __shared__ int   sidx[640];
    __shared__ float red[2][256];
    __shared__ float tot2[256];
    __shared__ bool  islast;

    int tid = threadIdx.x;
    int pbase = blockIdx.x * 32;
    for (int i = tid; i < 640; i += 256) sidx[i] = idx[pbase * 20 + i];
    __syncthreads();

    int m = tid & 63, slot = tid >> 6;
    float fs = 0.f, fq = 0.f;
#pragma unroll
    for (int i = 0; i < 8; i++) {
        int pl = slot * 8 + i;
        int p = pbase + pl;
        float y2 = g_y[p * 128 + 64 + m];
        int rowb = (p & ~1023) * 128;
        const int* ip = &sidx[pl * 20];
        float vmax = -1e30f, vmin = 1e30f;
#pragma unroll
        for (int k = 0; k < 20; k++) {
            float v = g_y[rowb + ip[k] * 128 + m] + y2;
            fs += v;
            fq += v * v;
            vmax = fmaxf(vmax, v);
            vmin = fminf(vmin, v);
        }
        g_hmax[p * 64 + m] = vmax;
        g_hmin[p * 64 + m] = vmin;
    }
    red[0][tid] = fs;
    red[1][tid] = fq;
    __syncthreads();
    if (tid < 64) {
        float s = red[0][tid] + red[0][tid + 64] + red[0][tid + 128] + red[0][tid + 192];
        float q = red[1][tid] + red[1][tid + 64] + red[1][tid + 128] + red[1][tid + 192];
        g_part1[tid * 256 + blockIdx.x] = s;
        g_part1[(64 + tid) * 256 + blockIdx.x] = q;
    }
    __threadfence();
    __syncthreads();
    if (tid == 0) {
        int old = atomicAdd(&g_cntB, 1);
        islast = (old == 255);
    }
    __syncthreads();
    if (!islast) return;
    __threadfence();

    {
        int col = tid & 127, half = tid >> 7;
        const float4* p4 = reinterpret_cast<const float4*>(&g_part1[col * 256 + half * 128]);
        float s = 0.f;
#pragma unroll 8
        for (int r = 0; r < 32; r++) {
            float4 v = p4[r];
            s += v.x + v.y + v.z + v.w;
        }
        red[0][tid] = s;
    }
    __syncthreads();
    if (tid < 128) tot2[tid] = red[0][tid] + red[0][tid + 128];
    __syncthreads();
    if (tid < 64) {
        float inv = 1.f / (float)CNT1;
        float mu = tot2[tid] * inv;
        float var = tot2[64 + tid] * inv - mu * mu;
        float sc = gamma1[tid] * rsqrtf(var + EPS);
        g_bn1[tid] = sc;
        g_bn1[64 + tid] = beta1[tid] - mu * sc;
        if (tid == 0) g_cntB = 0;
    }
}

// ---------------------------------------------------------------------------
// kC: terminal kernel. grid (4,64), 256 thr, 2 blocks/SM -> all 256 resident.
// Two p-tiles per block, accs in regs; BN2 partials; grid barrier; last block
// finalizes BN2; all apply affine+leaky from regs and store out once.
// ---------------------------------------------------------------------------
__global__ void __launch_bounds__(256, 2) kC_gemm2(const float* __restrict__ W2,
                                                   const float* __restrict__ gamma2,
                                                   const float* __restrict__ beta2,
                                                   float* __restrict__ out) {
    __shared__ float sv[2][64][68];
    __shared__ float sw[128][20];
    __shared__ float sbn[128];
    __shared__ float ssum[8][32];
    __shared__ float ssq[8][32];
    __shared__ bool  islast;

    int tid = threadIdx.x;
    int lane = tid & 31, w = tid >> 5;
    int grp = lane >> 2, tig = lane & 3;
    int m_base = (w >> 2) * 32;
    int n_base = (w & 3) * 32;
    int d0 = blockIdx.x * 128;
    int y = blockIdx.y;

    if (tid < 128) sbn[tid] = g_bn1[tid];
    __syncthreads();

#pragma unroll
    for (int t2 = 0; t2 < 2; t2++) {
        int p0 = (y + t2 * 64) * 64;
#pragma unroll
        for (int i = 0; i < 16; i++) {
            int e = tid + i * 256;
            int pt = e >> 6, m = e & 63;
            float sc = sbn[m], bi = sbn[64 + m];
            float h = (sc >= 0.f) ? g_hmax[(p0 + pt) * 64 + m] : g_hmin[(p0 + pt) * 64 + m];
            float v = sc * h + bi;
            sv[t2][pt][m] = fmaxf(v, 0.2f * v);
        }
    }

    float acc[2][2][4][4];
#pragma unroll
    for (int t2 = 0; t2 < 2; t2++)
#pragma unroll
        for (int r = 0; r < 2; r++)
#pragma unroll
            for (int j = 0; j < 4; j++)
#pragma unroll
                for (int q = 0; q < 4; q++) acc[t2][r][j][q] = 0.f;

    for (int t = 0; t < 4; t++) {
        int k0 = t * 16;
        {
            int wrow = tid >> 1;
            int seg = (tid & 1) * 8;
            *reinterpret_cast<float4*>(&sw[wrow][seg]) =
                *reinterpret_cast<const float4*>(&W2[(d0 + wrow) * 64 + k0 + seg]);
            *reinterpret_cast<float4*>(&sw[wrow][seg + 4]) =
                *reinterpret_cast<const float4*>(&W2[(d0 + wrow) * 64 + k0 + seg + 4]);
        }
        __syncthreads();
#pragma unroll
        for (int ks = 0; ks < 16; ks += 8) {
            float bh[4][2], bl[4][2];
#pragma unroll
            for (int j = 0; j < 4; j++) {
                int nc = n_base + j * 8 + grp;
                tf32_split(sw[nc][ks + tig],     bh[j][0], bl[j][0]);
                tf32_split(sw[nc][ks + tig + 4], bh[j][1], bl[j][1]);
            }
#pragma unroll
            for (int t2 = 0; t2 < 2; t2++) {
                float ah[2][4], al[2][4];
#pragma unroll
                for (int r = 0; r < 2; r++) {
                    int mr = m_base + r * 16;
                    tf32_split(sv[t2][mr + grp][k0 + ks + tig],         ah[r][0], al[r][0]);
                    tf32_split(sv[t2][mr + grp + 8][k0 + ks + tig],     ah[r][1], al[r][1]);
                    tf32_split(sv[t2][mr + grp][k0 + ks + tig + 4],     ah[r][2], al[r][2]);
                    tf32_split(sv[t2][mr + grp + 8][k0 + ks + tig + 4], ah[r][3], al[r][3]);
                }
#pragma unroll
                for (int r = 0; r < 2; r++)
#pragma unroll
                    for (int j = 0; j < 4; j++) {
                        mma_tf32(acc[t2][r][j], ah[r], bh[j]);
                        mma_tf32(acc[t2][r][j], al[r], bh[j]);
                        mma_tf32(acc[t2][r][j], ah[r], bl[j]);
                    }
            }
        }
        __syncthreads();
    }

#pragma unroll
    for (int t2 = 0; t2 < 2; t2++) {
        float ts[8], tq[8];
#pragma unroll
        for (int i = 0; i < 8; i++) { ts[i] = 0.f; tq[i] = 0.f; }
#pragma unroll
        for (int r = 0; r < 2; r++)
#pragma unroll
            for (int j = 0; j < 4; j++)
#pragma unroll
                for (int q = 0; q < 2; q++) {
                    float a0 = acc[t2][r][j][q], a1 = acc[t2][r][j][2 + q];
                    ts[j * 2 + q] += a0 + a1;
                    tq[j * 2 + q] += a0 * a0 + a1 * a1;
                }
#pragma unroll
        for (int i = 0; i < 8; i++) {
#pragma unroll
            for (int off = 4; off < 32; off <<= 1) {
                ts[i] += __shfl_xor_sync(0xffffffffu, ts[i], off);
                tq[i] += __shfl_xor_sync(0xffffffffu, tq[i], off);
            }
        }
        if (lane < 4) {
#pragma unroll
            for (int j = 0; j < 4; j++)
#pragma unroll
                for (int q = 0; q < 2; q++) {
                    ssum[w][j * 8 + 2 * lane + q] = ts[j * 2 + q];
                    ssq[w][j * 8 + 2 * lane + q]  = tq[j * 2 + q];
                }
        }
        __syncthreads();
        if (tid < 128) {
            int g = tid >> 5, c = tid & 31;
            float s = ssum[g][c] + ssum[g + 4][c];
            float q = ssq[g][c] + ssq[g + 4][c];
            int col = d0 + g * 32 + c;
            g_p2s[col * 128 + y + t2 * 64] = s;
            g_p2q[col * 128 + y + t2 * 64] = q;
        }
        __syncthreads();
    }

    __threadfence();
    __syncthreads();
    if (tid == 0) {
        int old = atomicAdd(&g_cntC, 1);
        islast = (old == 255);
    }
    __syncthreads();
    if (islast) {
        __threadfence();
#pragma unroll
        for (int cc = 0; cc < 2; cc++) {
            int col = tid + cc * 256;
            const float4* p4s = reinterpret_cast<const float4*>(&g_p2s[col * 128]);
            const float4* p4q = reinterpret_cast<const float4*>(&g_p2q[col * 128]);
            float s = 0.f, q = 0.f;
#pragma unroll 8
            for (int r = 0; r < 32; r++) {
                float4 a = p4s[r];
                float4 b = p4q[r];
                s += a.x + a.y + a.z + a.w;
                q += b.x + b.y + b.z + b.w;
            }
            float inv = 1.f / (float)CNT2;
            float mu = s * inv;
            float var = q * inv - mu * mu;
            float sc = gamma2[col] * rsqrtf(var + EPS);
            g_bn2[col] = sc;
            g_bn2[512 + col] = beta2[col] - mu * sc;
        }
        __threadfence();
        __syncthreads();
        if (tid == 0) atomicExch(&g_flagC, 1);
    }
    if (tid == 0) {
        while (atomicAdd(&g_flagC, 0) == 0) __nanosleep(64);
    }
    __syncthreads();
    __threadfence();

    float scv[4][2], biv[4][2];
#pragma unroll
    for (int j = 0; j < 4; j++) {
        int col = d0 + n_base + j * 8 + 2 * tig;
        scv[j][0] = g_bn2[col];
        scv[j][1] = g_bn2[col + 1];
        biv[j][0] = g_bn2[512 + col];
        biv[j][1] = g_bn2[513 + col];
    }
#pragma unroll
    for (int t2 = 0; t2 < 2; t2++) {
        int p0 = (y + t2 * 64) * 64;
#pragma unroll
        for (int r = 0; r < 2; r++) {
            int prow = p0 + m_base + r * 16 + grp;
#pragma unroll
            for (int j = 0; j < 4; j++) {
                int col = d0 + n_base + j * 8 + 2 * tig;
                float v0 = scv[j][0] * acc[t2][r][j][0] + biv[j][0];
                float v1 = scv[j][1] * acc[t2][r][j][1] + biv[j][1];
                float v2 = scv[j][0] * acc[t2][r][j][2] + biv[j][0];
                float v3 = scv[j][1] * acc[t2][r][j][3] + biv[j][1];
                v0 = fmaxf(v0, 0.2f * v0);
                v1 = fmaxf(v1, 0.2f * v1);
                v2 = fmaxf(v2, 0.2f * v2);
                v3 = fmaxf(v3, 0.2f * v3);
                *reinterpret_cast<float2*>(&out[prow * 512 + col]) = make_float2(v0, v1);
                *reinterpret_cast<float2*>(&out[(prow + 8) * 512 + col]) = make_float2(v2, v3);
            }
        }
    }

    __threadfence();
    __syncthreads();
    if (tid == 0) {
        int old = atomicAdd(&g_cntD, 1);
        if (old == 255) {
            g_cntC = 0;
            g_cntD = 0;
            g_flagC = 0;
        }
    }
}

// ---------------------------------------------------------------------------
extern "C" void kernel_launch(void* const* d_in, const int* in_sizes, int n_in,
                              void* d_out, int out_size) {
    const float* x      = (const float*)d_in[0];
    const int*   idx    = (const int*)  d_in[1];
    const float* W1     = (const float*)d_in[2];
    const float* gamma1 = (const float*)d_in[3];
    const float* beta1  = (const float*)d_in[4];
    const float* W2     = (const float*)d_in[5];
    const float* gamma2 = (const float*)d_in[6];
    const float* beta2  = (const float*)d_in[7];
    float* out = (float*)d_out;

    k0_prepw<<<256, 256>>>(W1);
    kA_gemm1<<<256, 256>>>(x);
    kB_gather<<<256, 256>>>(idx, gamma1, beta1);
    kC_gemm2<<<dim3(4, 64), 256>>>(W2, gamma2, beta2, out);
}

// round 9
// speedup vs baseline: 1.3232x; 1.3232x over previous
#include <cuda_runtime.h>
#include <cuda_bf16.h>
#include <cstdint>

#define Bb   8
#define Nn   1024
#define Cc   512
#define Kk   20
#define Mm   64
#define Pp   (Bb * Nn)        // 8192 points
#define CNT1 (Pp * Kk)        // 163840 samples for BN1
#define CNT2 Pp               // 8192 samples for BN2
#define EPS  1e-5f

// Scratch (no cudaMalloc allowed)
__device__ uint32_t g_W1h[128 * 256];   // folded W1' hi, packed bf16 pairs [n][kpair]
__device__ uint32_t g_W1l[128 * 256];   // folded W1' lo
__device__ float g_y[Pp * 128];         // per-point y1(0:64) | y2(64:128)
__device__ float g_hmax[Pp * 64];
__device__ float g_hmin[Pp * 64];
__device__ float g_part1[128 * 256];    // transposed: [col(sum64|sq64)][block 256]
__device__ float g_bn1[128];            // scale(64) | bias(64)
__device__ float g_p2s[512 * 128];      // transposed: [col][ptile 128]
__device__ float g_p2q[512 * 128];
__device__ float g_bn2[1024];           // scale(512) | bias(512)
__device__ int   g_cntB = 0;
__device__ int   g_cntC = 0;
__device__ int   g_cntD = 0;
__device__ int   g_flagC = 0;

__device__ __forceinline__ float tf32_rna(float v) {
    uint32_t u;
    asm("cvt.rna.tf32.f32 %0, %1;" : "=r"(u) : "f"(v));
    return __uint_as_float(u);
}

__device__ __forceinline__ void mma_tf32(float* d, const float* a, const float* b) {
    asm volatile(
        "mma.sync.aligned.m16n8k8.row.col.f32.tf32.tf32.f32 "
        "{%0,%1,%2,%3}, {%4,%5,%6,%7}, {%8,%9}, {%0,%1,%2,%3};"
        : "+f"(d[0]), "+f"(d[1]), "+f"(d[2]), "+f"(d[3])
        : "r"(__float_as_uint(a[0])), "r"(__float_as_uint(a[1])),
          "r"(__float_as_uint(a[2])), "r"(__float_as_uint(a[3])),
          "r"(__float_as_uint(b[0])), "r"(__float_as_uint(b[1])));
}

__device__ __forceinline__ void tf32_split(float v, float& hi, float& lo) {
    hi = tf32_rna(v);
    lo = tf32_rna(v - hi);
}

__device__ __forceinline__ void mma_bf16(float* d, const uint32_t* a, const uint32_t* b) {
    asm volatile(
        "mma.sync.aligned.m16n8k16.row.col.f32.bf16.bf16.f32 "
        "{%0,%1,%2,%3}, {%4,%5,%6,%7}, {%8,%9}, {%0,%1,%2,%3};"
        : "+f"(d[0]), "+f"(d[1]), "+f"(d[2]), "+f"(d[3])
        : "r"(a[0]), "r"(a[1]), "r"(a[2]), "r"(a[3]),
          "r"(b[0]), "r"(b[1]));
}

__device__ __forceinline__ uint32_t pack_bf16(float a, float b) {
    __nv_bfloat162 t = __floats2bfloat162_rn(a, b);   // a -> low half, b -> high half
    return *reinterpret_cast<uint32_t*>(&t);
}

__device__ __forceinline__ float bf16_round(float v) {
    return __bfloat162float(__float2bfloat16_rn(v));
}

// ---------------------------------------------------------------------------
// k0: fold W1 [64][1024] -> W1' [128][512], split to bf16 hi/lo packed pairs
// ---------------------------------------------------------------------------
__global__ void k0_prepw(const float* __restrict__ W1) {
    int i = blockIdx.x * 256 + threadIdx.x;      // 0..32767
    int n = i >> 8, kp = i & 255;
    int c = kp * 2;
    float v0, v1;
    if (n < 64) {
        float2 a = *reinterpret_cast<const float2*>(&W1[n * 1024 + c]);
        v0 = a.x; v1 = a.y;
    } else {
        int m = n - 64;
        float2 a = *reinterpret_cast<const float2*>(&W1[m * 1024 + c]);
        float2 b = *reinterpret_cast<const float2*>(&W1[m * 1024 + 512 + c]);
        v0 = b.x - a.x; v1 = b.y - a.y;
    }
    float h0 = bf16_round(v0), h1 = bf16_round(v1);
    g_W1h[i] = pack_bf16(v0, v1);
    g_W1l[i] = pack_bf16(v0 - h0, v1 - h1);
}

// ---------------------------------------------------------------------------
// kA: GEMM1 y[8192][128] = x @ W1'^T  via bf16 hi/lo 3-term m16n8k16 MMA.
// Tile 64p x 128n, BK=16 (8 pairs), double-buffered, reg prefetch,
// 256 thr (8 warps: 2m x 4n, warp = 32p x 32n), grid=128. 1 sync/iter.
// smem pair-stride 12: conflict-free fragment reads.
// ---------------------------------------------------------------------------
__global__ void __launch_bounds__(256) kA_gemm1(const float* __restrict__ x) {
    __shared__ uint32_t sxh[2][64][12], sxl[2][64][12];
    __shared__ uint32_t swh[2][128][12], swl[2][128][12];

    int tid = threadIdx.x;
    int lane = tid & 31, w = tid >> 5;
    int grp = lane >> 2, tig = lane & 3;
    int m_base = (w >> 2) * 32;     // 0 or 32
    int n_base = (w & 3) * 32;      // 0,32,64,96
    int p0 = blockIdx.x * 64;

    int xrow = tid >> 2;            // 0..63
    int xq = tid & 3;               // float4 at elem 4*xq -> pairs 2xq, 2xq+1
    int wrow = tid >> 1;            // 0..127
    int wseg = (tid & 1) * 4;       // pairs wseg..wseg+3

    float acc[2][4][4];
#pragma unroll
    for (int r = 0; r < 2; r++)
#pragma unroll
        for (int j = 0; j < 4; j++)
#pragma unroll
            for (int q = 0; q < 4; q++) acc[r][j][q] = 0.f;

    float4 rx;
    uint4 rwh, rwl;
    // prefetch tile 0
    rx  = *reinterpret_cast<const float4*>(&x[(p0 + xrow) * 512 + 4 * xq]);
    rwh = *reinterpret_cast<const uint4*>(&g_W1h[wrow * 256 + wseg]);
    rwl = *reinterpret_cast<const uint4*>(&g_W1l[wrow * 256 + wseg]);
    {
        float h0 = bf16_round(rx.x), h1 = bf16_round(rx.y);
        float h2 = bf16_round(rx.z), h3 = bf16_round(rx.w);
        sxh[0][xrow][2 * xq]     = pack_bf16(rx.x, rx.y);
        sxh[0][xrow][2 * xq + 1] = pack_bf16(rx.z, rx.w);
        sxl[0][xrow][2 * xq]     = pack_bf16(rx.x - h0, rx.y - h1);
        sxl[0][xrow][2 * xq + 1] = pack_bf16(rx.z - h2, rx.w - h3);
        *reinterpret_cast<uint4*>(&swh[0][wrow][wseg]) = rwh;
        *reinterpret_cast<uint4*>(&swl[0][wrow][wseg]) = rwl;
    }
    __syncthreads();

    int cur = 0;
    for (int t = 0; t < 32; t++) {
        if (t < 31) {
            int kb = (t + 1) * 16;
            rx  = *reinterpret_cast<const float4*>(&x[(p0 + xrow) * 512 + kb + 4 * xq]);
            rwh = *reinterpret_cast<const uint4*>(&g_W1h[wrow * 256 + (t + 1) * 8 + wseg]);
            rwl = *reinterpret_cast<const uint4*>(&g_W1l[wrow * 256 + (t + 1) * 8 + wseg]);
        }
        // fragments (pure LDS, no conversion)
        uint32_t ah[2][4], al[2][4], bh[4][2], bl[4][2];
#pragma unroll
        for (int r = 0; r < 2; r++) {
            int mr = m_base + r * 16;
            ah[r][0] = sxh[cur][mr + grp][tig];
            ah[r][1] = sxh[cur][mr + grp + 8][tig];
            ah[r][2] = sxh[cur][mr + grp][4 + tig];
            ah[r][3] = sxh[cur][mr + grp + 8][4 + tig];
            al[r][0] = sxl[cur][mr + grp][tig];
            al[r][1] = sxl[cur][mr + grp + 8][tig];
            al[r][2] = sxl[cur][mr + grp][4 + tig];
            al[r][3] = sxl[cur][mr + grp + 8][4 + tig];
        }
#pragma unroll
        for (int j = 0; j < 4; j++) {
            int nc = n_base + j * 8 + grp;
            bh[j][0] = swh[cur][nc][tig];
            bh[j][1] = swh[cur][nc][4 + tig];
            bl[j][0] = swl[cur][nc][tig];
            bl[j][1] = swl[cur][nc][4 + tig];
        }
#pragma unroll
        for (int r = 0; r < 2; r++)
#pragma unroll
            for (int j = 0; j < 4; j++) {
                mma_bf16(acc[r][j], ah[r], bh[j]);
                mma_bf16(acc[r][j], al[r], bh[j]);
                mma_bf16(acc[r][j], ah[r], bl[j]);
            }
        if (t < 31) {
            int nxt = cur ^ 1;
            float h0 = bf16_round(rx.x), h1 = bf16_round(rx.y);
            float h2 = bf16_round(rx.z), h3 = bf16_round(rx.w);
            sxh[nxt][xrow][2 * xq]     = pack_bf16(rx.x, rx.y);
            sxh[nxt][xrow][2 * xq + 1] = pack_bf16(rx.z, rx.w);
            sxl[nxt][xrow][2 * xq]     = pack_bf16(rx.x - h0, rx.y - h1);
            sxl[nxt][xrow][2 * xq + 1] = pack_bf16(rx.z - h2, rx.w - h3);
            *reinterpret_cast<uint4*>(&swh[nxt][wrow][wseg]) = rwh;
            *reinterpret_cast<uint4*>(&swl[nxt][wrow][wseg]) = rwl;
            __syncthreads();
            cur = nxt;
        }
    }

#pragma unroll
    for (int r = 0; r < 2; r++) {
        int prow = p0 + m_base + r * 16 + grp;
#pragma unroll
        for (int j = 0; j < 4; j++) {
            int col = n_base + j * 8 + 2 * tig;
            *reinterpret_cast<float2*>(&g_y[prow * 128 + col]) =
                make_float2(acc[r][j][0], acc[r][j][1]);
            *reinterpret_cast<float2*>(&g_y[(prow + 8) * 128 + col]) =
                make_float2(acc[r][j][2], acc[r][j][3]);
        }
    }
}

// ---------------------------------------------------------------------------
// kB: gather (max/min + sum/sumsq) + last-block BN1 finalize. grid=256, 256thr
// ---------------------------------------------------------------------------
__global__ void __launch_bounds__(256) kB_gather(const int* __restrict__ idx,
                                                 const float* __restrict__ gamma1,
                                                 const float* __restrict__ beta1) {
    __shared__ int   sidx[640];
    __shared__ float red[2][256];
    __shared__ float tot2[256];
    __shared__ bool  islast;

    int tid = threadIdx.x;
    int pbase = blockIdx.x * 32;
    for (int i = tid; i < 640; i += 256) sidx[i] = idx[pbase * 20 + i];
    __syncthreads();

    int m = tid & 63, slot = tid >> 6;
    float fs = 0.f, fq = 0.f;
#pragma unroll
    for (int i = 0; i < 8; i++) {
        int pl = slot * 8 + i;
        int p = pbase + pl;
        float y2 = g_y[p * 128 + 64 + m];
        int rowb = (p & ~1023) * 128;
        const int* ip = &sidx[pl * 20];
        float vmax = -1e30f, vmin = 1e30f;
#pragma unroll
        for (int k = 0; k < 20; k++) {
            float v = g_y[rowb + ip[k] * 128 + m] + y2;
            fs += v;
            fq += v * v;
            vmax = fmaxf(vmax, v);
            vmin = fminf(vmin, v);
        }
        g_hmax[p * 64 + m] = vmax;
        g_hmin[p * 64 + m] = vmin;
    }
    red[0][tid] = fs;
    red[1][tid] = fq;
    __syncthreads();
    if (tid < 64) {
        float s = red[0][tid] + red[0][tid + 64] + red[0][tid + 128] + red[0][tid + 192];
        float q = red[1][tid] + red[1][tid + 64] + red[1][tid + 128] + red[1][tid + 192];
        g_part1[tid * 256 + blockIdx.x] = s;
        g_part1[(64 + tid) * 256 + blockIdx.x] = q;
    }
    __threadfence();
    __syncthreads();
    if (tid == 0) {
        int old = atomicAdd(&g_cntB, 1);
        islast = (old == 255);
    }
    __syncthreads();
    if (!islast) return;
    __threadfence();

    {
        int col = tid & 127, half = tid >> 7;
        const float4* p4 = reinterpret_cast<const float4*>(&g_part1[col * 256 + half * 128]);
        float s = 0.f;
#pragma unroll 8
        for (int r = 0; r < 32; r++) {
            float4 v = p4[r];
            s += v.x + v.y + v.z + v.w;
        }
        red[0][tid] = s;
    }
    __syncthreads();
    if (tid < 128) tot2[tid] = red[0][tid] + red[0][tid + 128];
    __syncthreads();
    if (tid < 64) {
        float inv = 1.f / (float)CNT1;
        float mu = tot2[tid] * inv;
        float var = tot2[64 + tid] * inv - mu * mu;
        float sc = gamma1[tid] * rsqrtf(var + EPS);
        g_bn1[tid] = sc;
        g_bn1[64 + tid] = beta1[tid] - mu * sc;
        if (tid == 0) g_cntB = 0;
    }
}

// ---------------------------------------------------------------------------
// kC: terminal kernel (unchanged from best run). grid (4,64), 256 thr,
// 2 blocks/SM resident; grid barrier; last block finalizes BN2; all apply
// affine+leaky from regs and store out once.
// ---------------------------------------------------------------------------
__global__ void __launch_bounds__(256, 2) kC_gemm2(const float* __restrict__ W2,
                                                   const float* __restrict__ gamma2,
                                                   const float* __restrict__ beta2,
                                                   float* __restrict__ out) {
    __shared__ float sv[2][64][68];
    __shared__ float sw[128][20];
    __shared__ float sbn[128];
    __shared__ float ssum[8][32];
    __shared__ float ssq[8][32];
    __shared__ bool  islast;

    int tid = threadIdx.x;
    int lane = tid & 31, w = tid >> 5;
    int grp = lane >> 2, tig = lane & 3;
    int m_base = (w >> 2) * 32;
    int n_base = (w & 3) * 32;
    int d0 = blockIdx.x * 128;
    int y = blockIdx.y;

    if (tid < 128) sbn[tid] = g_bn1[tid];
    __syncthreads();

#pragma unroll
    for (int t2 = 0; t2 < 2; t2++) {
        int p0 = (y + t2 * 64) * 64;
#pragma unroll
        for (int i = 0; i < 16; i++) {
            int e = tid + i * 256;
            int pt = e >> 6, m = e & 63;
            float sc = sbn[m], bi = sbn[64 + m];
            float h = (sc >= 0.f) ? g_hmax[(p0 + pt) * 64 + m] : g_hmin[(p0 + pt) * 64 + m];
            float v = sc * h + bi;
            sv[t2][pt][m] = fmaxf(v, 0.2f * v);
        }
    }

    float acc[2][2][4][4];
#pragma unroll
    for (int t2 = 0; t2 < 2; t2++)
#pragma unroll
        for (int r = 0; r < 2; r++)
#pragma unroll
            for (int j = 0; j < 4; j++)
#pragma unroll
                for (int q = 0; q < 4; q++) acc[t2][r][j][q] = 0.f;

    for (int t = 0; t < 4; t++) {
        int k0 = t * 16;
        {
            int wrow = tid >> 1;
            int seg = (tid & 1) * 8;
            *reinterpret_cast<float4*>(&sw[wrow][seg]) =
                *reinterpret_cast<const float4*>(&W2[(d0 + wrow) * 64 + k0 + seg]);
            *reinterpret_cast<float4*>(&sw[wrow][seg + 4]) =
                *reinterpret_cast<const float4*>(&W2[(d0 + wrow) * 64 + k0 + seg + 4]);
        }
        __syncthreads();
#pragma unroll
        for (int ks = 0; ks < 16; ks += 8) {
            float bh[4][2], bl[4][2];
#pragma unroll
            for (int j = 0; j < 4; j++) {
                int nc = n_base + j * 8 + grp;
                tf32_split(sw[nc][ks + tig],     bh[j][0], bl[j][0]);
                tf32_split(sw[nc][ks + tig + 4], bh[j][1], bl[j][1]);
            }
#pragma unroll
            for (int t2 = 0; t2 < 2; t2++) {
                float ah[2][4], al[2][4];
#pragma unroll
                for (int r = 0; r < 2; r++) {
                    int mr = m_base + r * 16;
                    tf32_split(sv[t2][mr + grp][k0 + ks + tig],         ah[r][0], al[r][0]);
                    tf32_split(sv[t2][mr + grp + 8][k0 + ks + tig],     ah[r][1], al[r][1]);
                    tf32_split(sv[t2][mr + grp][k0 + ks + tig + 4],     ah[r][2], al[r][2]);
                    tf32_split(sv[t2][mr + grp + 8][k0 + ks + tig + 4], ah[r][3], al[r][3]);
                }
#pragma unroll
                for (int r = 0; r < 2; r++)
#pragma unroll
                    for (int j = 0; j < 4; j++) {
                        mma_tf32(acc[t2][r][j], ah[r], bh[j]);
                        mma_tf32(acc[t2][r][j], al[r], bh[j]);
                        mma_tf32(acc[t2][r][j], ah[r], bl[j]);
                    }
            }
        }
        __syncthreads();
    }

#pragma unroll
    for (int t2 = 0; t2 < 2; t2++) {
        float ts[8], tq[8];
#pragma unroll
        for (int i = 0; i < 8; i++) { ts[i] = 0.f; tq[i] = 0.f; }
#pragma unroll
        for (int r = 0; r < 2; r++)
#pragma unroll
            for (int j = 0; j < 4; j++)
#pragma unroll
                for (int q = 0; q < 2; q++) {
                    float a0 = acc[t2][r][j][q], a1 = acc[t2][r][j][2 + q];
                    ts[j * 2 + q] += a0 + a1;
                    tq[j * 2 + q] += a0 * a0 + a1 * a1;
                }
#pragma unroll
        for (int i = 0; i < 8; i++) {
#pragma unroll
            for (int off = 4; off < 32; off <<= 1) {
                ts[i] += __shfl_xor_sync(0xffffffffu, ts[i], off);
                tq[i] += __shfl_xor_sync(0xffffffffu, tq[i], off);
            }
        }
        if (lane < 4) {
#pragma unroll
            for (int j = 0; j < 4; j++)
#pragma unroll
                for (int q = 0; q < 2; q++) {
                    ssum[w][j * 8 + 2 * lane + q] = ts[j * 2 + q];
                    ssq[w][j * 8 + 2 * lane + q]  = tq[j * 2 + q];
                }
        }
        __syncthreads();
        if (tid < 128) {
            int g = tid >> 5, c = tid & 31;
            float s = ssum[g][c] + ssum[g + 4][c];
            float q = ssq[g][c] + ssq[g + 4][c];
            int col = d0 + g * 32 + c;
            g_p2s[col * 128 + y + t2 * 64] = s;
            g_p2q[col * 128 + y + t2 * 64] = q;
        }
        __syncthreads();
    }

    __threadfence();
    __syncthreads();
    if (tid == 0) {
        int old = atomicAdd(&g_cntC, 1);
        islast = (old == 255);
    }
    __syncthreads();
    if (islast) {
        __threadfence();
#pragma unroll
        for (int cc = 0; cc < 2; cc++) {
            int col = tid + cc * 256;
            const float4* p4s = reinterpret_cast<const float4*>(&g_p2s[col * 128]);
            const float4* p4q = reinterpret_cast<const float4*>(&g_p2q[col * 128]);
            float s = 0.f, q = 0.f;
#pragma unroll 8
            for (int r = 0; r < 32; r++) {
                float4 a = p4s[r];
                float4 b = p4q[r];
                s += a.x + a.y + a.z + a.w;
                q += b.x + b.y + b.z + b.w;
            }
            float inv = 1.f / (float)CNT2;
            float mu = s * inv;
            float var = q * inv - mu * mu;
            float sc = gamma2[col] * rsqrtf(var + EPS);
            g_bn2[col] = sc;
            g_bn2[512 + col] = beta2[col] - mu * sc;
        }
        __threadfence();
        __syncthreads();
        if (tid == 0) atomicExch(&g_flagC, 1);
    }
    if (tid == 0) {
        while (atomicAdd(&g_flagC, 0) == 0) __nanosleep(64);
    }
    __syncthreads();
    __threadfence();

    float scv[4][2], biv[4][2];
#pragma unroll
    for (int j = 0; j < 4; j++) {
        int col = d0 + n_base + j * 8 + 2 * tig;
        scv[j][0] = g_bn2[col];
        scv[j][1] = g_bn2[col + 1];
        biv[j][0] = g_bn2[512 + col];
        biv[j][1] = g_bn2[513 + col];
    }
#pragma unroll
    for (int t2 = 0; t2 < 2; t2++) {
        int p0 = (y + t2 * 64) * 64;
#pragma unroll
        for (int r = 0; r < 2; r++) {
            int prow = p0 + m_base + r * 16 + grp;
#pragma unroll
            for (int j = 0; j < 4; j++) {
                int col = d0 + n_base + j * 8 + 2 * tig;
                float v0 = scv[j][0] * acc[t2][r][j][0] + biv[j][0];
                float v1 = scv[j][1] * acc[t2][r][j][1] + biv[j][1];
                float v2 = scv[j][0] * acc[t2][r][j][2] + biv[j][0];
                float v3 = scv[j][1] * acc[t2][r][j][3] + biv[j][1];
                v0 = fmaxf(v0, 0.2f * v0);
                v1 = fmaxf(v1, 0.2f * v1);
                v2 = fmaxf(v2, 0.2f * v2);
                v3 = fmaxf(v3, 0.2f * v3);
                *reinterpret_cast<float2*>(&out[prow * 512 + col]) = make_float2(v0, v1);
                *reinterpret_cast<float2*>(&out[(prow + 8) * 512 + col]) = make_float2(v2, v3);
            }
        }
    }

    __threadfence();
    __syncthreads();
    if (tid == 0) {
        int old = atomicAdd(&g_cntD, 1);
        if (old == 255) {
            g_cntC = 0;
            g_cntD = 0;
            g_flagC = 0;
        }
    }
}

// ---------------------------------------------------------------------------
extern "C" void kernel_launch(void* const* d_in, const int* in_sizes, int n_in,
                              void* d_out, int out_size) {
    const float* x      = (const float*)d_in[0];
    const int*   idx    = (const int*)  d_in[1];
    const float* W1     = (const float*)d_in[2];
    const float* gamma1 = (const float*)d_in[3];
    const float* beta1  = (const float*)d_in[4];
    const float* W2     = (const float*)d_in[5];
    const float* gamma2 = (const float*)d_in[6];
    const float* beta2  = (const float*)d_in[7];
    float* out = (float*)d_out;

    k0_prepw<<<128, 256>>>(W1);
    kA_gemm1<<<128, 256>>>(x);
    kB_gather<<<256, 256>>>(idx, gamma1, beta1);
    kC_gemm2<<<dim3(4, 64), 256>>>(W2, gamma2, beta2, out);
}

// round 10
// speedup vs baseline: 1.4275x; 1.0788x over previous
#include <cuda_runtime.h>
#include <cuda_bf16.h>
#include <cstdint>

#define Bb   8
#define Nn   1024
#define Cc   512
#define Kk   20
#define Mm   64
#define Pp   (Bb * Nn)        // 8192 points
#define CNT1 (Pp * Kk)        // 163840 samples for BN1
#define CNT2 Pp               // 8192 samples for BN2
#define EPS  1e-5f

// Scratch (no cudaMalloc allowed)
__device__ uint32_t g_W1h[128 * 256];   // folded W1' hi, packed bf16 pairs [n][kpair]
__device__ uint32_t g_W1l[128 * 256];   // folded W1' lo
__device__ uint32_t g_W2h[512 * 32];    // W2 hi, packed bf16 pairs [d][mpair]
__device__ uint32_t g_W2l[512 * 32];    // W2 lo
__device__ float g_y[Pp * 128];         // per-point y1(0:64) | y2(64:128)
__device__ float g_hmax[Pp * 64];
__device__ float g_hmin[Pp * 64];
__device__ float g_part1[128 * 256];    // transposed: [col(sum64|sq64)][block 256]
__device__ float g_bn1[128];            // scale(64) | bias(64)
__device__ float g_p2s[512 * 128];      // transposed: [col][ptile 128]
__device__ float g_p2q[512 * 128];
__device__ float g_bn2[1024];           // scale(512) | bias(512)
__device__ int   g_cntB = 0;
__device__ int   g_cntC = 0;
__device__ int   g_cntD = 0;
__device__ int   g_flagC = 0;

__device__ __forceinline__ void mma_bf16(float* d, const uint32_t* a, const uint32_t* b) {
    asm volatile(
        "mma.sync.aligned.m16n8k16.row.col.f32.bf16.bf16.f32 "
        "{%0,%1,%2,%3}, {%4,%5,%6,%7}, {%8,%9}, {%0,%1,%2,%3};"
        : "+f"(d[0]), "+f"(d[1]), "+f"(d[2]), "+f"(d[3])
        : "r"(a[0]), "r"(a[1]), "r"(a[2]), "r"(a[3]),
          "r"(b[0]), "r"(b[1]));
}

__device__ __forceinline__ uint32_t pack_bf16(float a, float b) {
    __nv_bfloat162 t = __floats2bfloat162_rn(a, b);
    return *reinterpret_cast<uint32_t*>(&t);
}

__device__ __forceinline__ float bf16_round(float v) {
    return __bfloat162float(__float2bfloat16_rn(v));
}

// ---------------------------------------------------------------------------
// k0: prep W1' (fold + bf16 hi/lo pairs) and W2 (bf16 hi/lo pairs). grid=192
// ---------------------------------------------------------------------------
__global__ void k0_prepw(const float* __restrict__ W1, const float* __restrict__ W2) {
    int i = blockIdx.x * 256 + threadIdx.x;      // 0..49151
    if (i < 32768) {
        int n = i >> 8, kp = i & 255;
        int c = kp * 2;
        float v0, v1;
        if (n < 64) {
            float2 a = *reinterpret_cast<const float2*>(&W1[n * 1024 + c]);
            v0 = a.x; v1 = a.y;
        } else {
            int m = n - 64;
            float2 a = *reinterpret_cast<const float2*>(&W1[m * 1024 + c]);
            float2 b = *reinterpret_cast<const float2*>(&W1[m * 1024 + 512 + c]);
            v0 = b.x - a.x; v1 = b.y - a.y;
        }
        float h0 = bf16_round(v0), h1 = bf16_round(v1);
        g_W1h[i] = pack_bf16(v0, v1);
        g_W1l[i] = pack_bf16(v0 - h0, v1 - h1);
    } else {
        int j = i - 32768;                       // 0..16383
        int d = j >> 5, mp = j & 31;
        float2 a = *reinterpret_cast<const float2*>(&W2[d * 64 + mp * 2]);
        float h0 = bf16_round(a.x), h1 = bf16_round(a.y);
        g_W2h[j] = pack_bf16(a.x, a.y);
        g_W2l[j] = pack_bf16(a.x - h0, a.y - h1);
    }
}

// ---------------------------------------------------------------------------
// kA: GEMM1 y = x @ W1'^T, bf16 hi/lo 3-term MMA. Tile 64p x 128n, BK=16,
// 512 threads (16 warps: 4m x 4n, warp = 16p x 32n), double-buffered,
// register prefetch, grid=128. Inner loop: pure LDS + MMA.
// ---------------------------------------------------------------------------
__global__ void __launch_bounds__(512) kA_gemm1(const float* __restrict__ x) {
    __shared__ uint32_t sxh[2][64][12], sxl[2][64][12];
    __shared__ uint32_t swh[2][128][12], swl[2][128][12];

    int tid = threadIdx.x;
    int lane = tid & 31, w = tid >> 5;
    int grp = lane >> 2, tig = lane & 3;
    int m_base = (w >> 2) * 16;     // 0,16,32,48
    int n_base = (w & 3) * 32;      // 0,32,64,96
    int p0 = blockIdx.x * 64;

    int xrow = tid >> 3;            // 0..63
    int xp = tid & 7;               // pair index 0..7 (cols 2xp, 2xp+1)
    int widx = tid & 255;
    int wrow = widx >> 1;           // 0..127
    int wseg = (widx & 1) * 4;      // pair 0 or 4
    const uint32_t* wg = (tid < 256 ? g_W1h : g_W1l) + wrow * 256;
    uint32_t* wsm = (tid < 256) ? &swh[0][0][0] : &swl[0][0][0];

    float acc[4][4];
#pragma unroll
    for (int j = 0; j < 4; j++)
#pragma unroll
        for (int q = 0; q < 4; q++) acc[j][q] = 0.f;

    float2 rx;
    uint4 rw;
    rx = *reinterpret_cast<const float2*>(&x[(p0 + xrow) * 512 + 2 * xp]);
    rw = *reinterpret_cast<const uint4*>(&wg[wseg]);
    {
        float h0 = bf16_round(rx.x), h1 = bf16_round(rx.y);
        sxh[0][xrow][xp] = pack_bf16(rx.x, rx.y);
        sxl[0][xrow][xp] = pack_bf16(rx.x - h0, rx.y - h1);
        *reinterpret_cast<uint4*>(wsm + wrow * 12 + wseg) = rw;
    }
    __syncthreads();

    int cur = 0;
    for (int t = 0; t < 32; t++) {
        if (t < 31) {
            int kb = (t + 1) * 16;
            rx = *reinterpret_cast<const float2*>(&x[(p0 + xrow) * 512 + kb + 2 * xp]);
            rw = *reinterpret_cast<const uint4*>(&wg[(t + 1) * 8 + wseg]);
        }
        uint32_t ah[4], al[4], bh[4][2], bl[4][2];
        ah[0] = sxh[cur][m_base + grp][tig];
        ah[1] = sxh[cur][m_base + grp + 8][tig];
        ah[2] = sxh[cur][m_base + grp][4 + tig];
        ah[3] = sxh[cur][m_base + grp + 8][4 + tig];
        al[0] = sxl[cur][m_base + grp][tig];
        al[1] = sxl[cur][m_base + grp + 8][tig];
        al[2] = sxl[cur][m_base + grp][4 + tig];
        al[3] = sxl[cur][m_base + grp + 8][4 + tig];
#pragma unroll
        for (int j = 0; j < 4; j++) {
            int nc = n_base + j * 8 + grp;
            bh[j][0] = swh[cur][nc][tig];
            bh[j][1] = swh[cur][nc][4 + tig];
            bl[j][0] = swl[cur][nc][tig];
            bl[j][1] = swl[cur][nc][4 + tig];
        }
#pragma unroll
        for (int j = 0; j < 4; j++) {
            mma_bf16(acc[j], ah, bh[j]);
            mma_bf16(acc[j], al, bh[j]);
            mma_bf16(acc[j], ah, bl[j]);
        }
        if (t < 31) {
            int nxt = cur ^ 1;
            float h0 = bf16_round(rx.x), h1 = bf16_round(rx.y);
            sxh[nxt][xrow][xp] = pack_bf16(rx.x, rx.y);
            sxl[nxt][xrow][xp] = pack_bf16(rx.x - h0, rx.y - h1);
            *reinterpret_cast<uint4*>(wsm + nxt * 1536 + wrow * 12 + wseg) = rw;
            __syncthreads();
            cur = nxt;
        }
    }

    {
        int prow = p0 + m_base + grp;
#pragma unroll
        for (int j = 0; j < 4; j++) {
            int col = n_base + j * 8 + 2 * tig;
            *reinterpret_cast<float2*>(&g_y[prow * 128 + col]) =
                make_float2(acc[j][0], acc[j][1]);
            *reinterpret_cast<float2*>(&g_y[(prow + 8) * 128 + col]) =
                make_float2(acc[j][2], acc[j][3]);
        }
    }
}

// ---------------------------------------------------------------------------
// kB: gather (max/min + sum/sumsq) + last-block BN1 finalize. grid=256, 256thr
// ---------------------------------------------------------------------------
__global__ void __launch_bounds__(256) kB_gather(const int* __restrict__ idx,
                                                 const float* __restrict__ gamma1,
                                                 const float* __restrict__ beta1) {
    __shared__ int   sidx[640];
    __shared__ float red[2][256];
    __shared__ float tot2[256];
    __shared__ bool  islast;

    int tid = threadIdx.x;
    int pbase = blockIdx.x * 32;
    for (int i = tid; i < 640; i += 256) sidx[i] = idx[pbase * 20 + i];
    __syncthreads();

    int m = tid & 63, slot = tid >> 6;
    float fs = 0.f, fq = 0.f;
#pragma unroll
    for (int i = 0; i < 8; i++) {
        int pl = slot * 8 + i;
        int p = pbase + pl;
        float y2 = g_y[p * 128 + 64 + m];
        int rowb = (p & ~1023) * 128;
        const int* ip = &sidx[pl * 20];
        float vmax = -1e30f, vmin = 1e30f;
#pragma unroll
        for (int k = 0; k < 20; k++) {
            float v = g_y[rowb + ip[k] * 128 + m] + y2;
            fs += v;
            fq += v * v;
            vmax = fmaxf(vmax, v);
            vmin = fminf(vmin, v);
        }
        g_hmax[p * 64 + m] = vmax;
        g_hmin[p * 64 + m] = vmin;
    }
    red[0][tid] = fs;
    red[1][tid] = fq;
    __syncthreads();
    if (tid < 64) {
        float s = red[0][tid] + red[0][tid + 64] + red[0][tid + 128] + red[0][tid + 192];
        float q = red[1][tid] + red[1][tid + 64] + red[1][tid + 128] + red[1][tid + 192];
        g_part1[tid * 256 + blockIdx.x] = s;
        g_part1[(64 + tid) * 256 + blockIdx.x] = q;
    }
    __threadfence();
    __syncthreads();
    if (tid == 0) {
        int old = atomicAdd(&g_cntB, 1);
        islast = (old == 255);
    }
    __syncthreads();
    if (!islast) return;
    __threadfence();

    {
        int col = tid & 127, half = tid >> 7;
        const float4* p4 = reinterpret_cast<const float4*>(&g_part1[col * 256 + half * 128]);
        float s = 0.f;
#pragma unroll 8
        for (int r = 0; r < 32; r++) {
            float4 v = p4[r];
            s += v.x + v.y + v.z + v.w;
        }
        red[0][tid] = s;
    }
    __syncthreads();
    if (tid < 128) tot2[tid] = red[0][tid] + red[0][tid + 128];
    __syncthreads();
    if (tid < 64) {
        float inv = 1.f / (float)CNT1;
        float mu = tot2[tid] * inv;
        float var = tot2[64 + tid] * inv - mu * mu;
        float sc = gamma1[tid] * rsqrtf(var + EPS);
        g_bn1[tid] = sc;
        g_bn1[64 + tid] = beta1[tid] - mu * sc;
        if (tid == 0) g_cntB = 0;
    }
}

// ---------------------------------------------------------------------------
// kC: terminal kernel, bf16 GEMM2. grid (4,64), 256 thr, 2 blocks/SM.
// Activations packed to bf16 hi/lo pairs in prologue (stride 36: conflict-
// free). W2 B-frags via register-prefetched LDG (L2-resident). Grid barrier,
// last block finalizes BN2, all apply affine+leaky from regs, store out once.
// ---------------------------------------------------------------------------
__global__ void __launch_bounds__(256, 2) kC_gemm2(const float* __restrict__ gamma2,
                                                   const float* __restrict__ beta2,
                                                   float* __restrict__ out) {
    __shared__ uint32_t svh[2][64][36], svl[2][64][36];
    __shared__ float sbn[128];
    __shared__ float ssum[8][32];
    __shared__ float ssq[8][32];
    __shared__ bool  islast;

    int tid = threadIdx.x;
    int lane = tid & 31, w = tid >> 5;
    int grp = lane >> 2, tig = lane & 3;
    int m_base = (w >> 2) * 32;     // p-offset: 0 or 32
    int n_base = (w & 3) * 32;      // d-offset: 0,32,64,96
    int d0 = blockIdx.x * 128;
    int y = blockIdx.y;

    if (tid < 128) sbn[tid] = g_bn1[tid];
    __syncthreads();

    // prologue: build packed bf16 hi/lo activation tiles
#pragma unroll
    for (int t2 = 0; t2 < 2; t2++) {
        int p0 = (y + t2 * 64) * 64;
#pragma unroll
        for (int i = 0; i < 8; i++) {
            int e = tid + i * 256;          // 0..2047
            int pt = e >> 5, mp = e & 31;
            int m0 = 2 * mp;
            float sc0 = sbn[m0], bi0 = sbn[64 + m0];
            float sc1 = sbn[m0 + 1], bi1 = sbn[64 + m0 + 1];
            const float* s0 = (sc0 >= 0.f) ? g_hmax : g_hmin;
            const float* s1 = (sc1 >= 0.f) ? g_hmax : g_hmin;
            float h0 = s0[(p0 + pt) * 64 + m0];
            float h1 = s1[(p0 + pt) * 64 + m0 + 1];
            float v0 = sc0 * h0 + bi0;
            float v1 = sc1 * h1 + bi1;
            v0 = fmaxf(v0, 0.2f * v0);
            v1 = fmaxf(v1, 0.2f * v1);
            float r0 = bf16_round(v0), r1 = bf16_round(v1);
            svh[t2][pt][mp] = pack_bf16(v0, v1);
            svl[t2][pt][mp] = pack_bf16(v0 - r0, v1 - r1);
        }
    }
    __syncthreads();

    float acc[2][2][4][4];
#pragma unroll
    for (int t2 = 0; t2 < 2; t2++)
#pragma unroll
        for (int r = 0; r < 2; r++)
#pragma unroll
            for (int j = 0; j < 4; j++)
#pragma unroll
                for (int q = 0; q < 4; q++) acc[t2][r][j][q] = 0.f;

    // B-fragment prefetch (chunk 0) from global W2 pairs
    uint32_t bhc[4][2], blc[4][2], bhn[4][2], bln[4][2];
#pragma unroll
    for (int j = 0; j < 4; j++) {
        int nc = d0 + n_base + j * 8 + grp;
        bhc[j][0] = g_W2h[nc * 32 + tig];
        bhc[j][1] = g_W2h[nc * 32 + 4 + tig];
        blc[j][0] = g_W2l[nc * 32 + tig];
        blc[j][1] = g_W2l[nc * 32 + 4 + tig];
    }

    for (int ch = 0; ch < 4; ch++) {
        if (ch < 3) {
            int kb = (ch + 1) * 8;
#pragma unroll
            for (int j = 0; j < 4; j++) {
                int nc = d0 + n_base + j * 8 + grp;
                bhn[j][0] = g_W2h[nc * 32 + kb + tig];
                bhn[j][1] = g_W2h[nc * 32 + kb + 4 + tig];
                bln[j][0] = g_W2l[nc * 32 + kb + tig];
                bln[j][1] = g_W2l[nc * 32 + kb + 4 + tig];
            }
        }
        int kb = ch * 8;
#pragma unroll
        for (int t2 = 0; t2 < 2; t2++) {
            uint32_t ah[2][4], al[2][4];
#pragma unroll
            for (int r = 0; r < 2; r++) {
                int mr = m_base + r * 16;
                ah[r][0] = svh[t2][mr + grp][kb + tig];
                ah[r][1] = svh[t2][mr + grp + 8][kb + tig];
                ah[r][2] = svh[t2][mr + grp][kb + 4 + tig];
                ah[r][3] = svh[t2][mr + grp + 8][kb + 4 + tig];
                al[r][0] = svl[t2][mr + grp][kb + tig];
                al[r][1] = svl[t2][mr + grp + 8][kb + tig];
                al[r][2] = svl[t2][mr + grp][kb + 4 + tig];
                al[r][3] = svl[t2][mr + grp + 8][kb + 4 + tig];
            }
#pragma unroll
            for (int r = 0; r < 2; r++)
#pragma unroll
                for (int j = 0; j < 4; j++) {
                    mma_bf16(acc[t2][r][j], ah[r], bhc[j]);
                    mma_bf16(acc[t2][r][j], al[r], bhc[j]);
                    mma_bf16(acc[t2][r][j], ah[r], blc[j]);
                }
        }
        if (ch < 3) {
#pragma unroll
            for (int j = 0; j < 4; j++) {
                bhc[j][0] = bhn[j][0]; bhc[j][1] = bhn[j][1];
                blc[j][0] = bln[j][0]; blc[j][1] = bln[j][1];
            }
        }
    }

    // BN2 partial stats
#pragma unroll
    for (int t2 = 0; t2 < 2; t2++) {
        float ts[8], tq[8];
#pragma unroll
        for (int i = 0; i < 8; i++) { ts[i] = 0.f; tq[i] = 0.f; }
#pragma unroll
        for (int r = 0; r < 2; r++)
#pragma unroll
            for (int j = 0; j < 4; j++)
#pragma unroll
                for (int q = 0; q < 2; q++) {
                    float a0 = acc[t2][r][j][q], a1 = acc[t2][r][j][2 + q];
                    ts[j * 2 + q] += a0 + a1;
                    tq[j * 2 + q] += a0 * a0 + a1 * a1;
                }
#pragma unroll
        for (int i = 0; i < 8; i++) {
#pragma unroll
            for (int off = 4; off < 32; off <<= 1) {
                ts[i] += __shfl_xor_sync(0xffffffffu, ts[i], off);
                tq[i] += __shfl_xor_sync(0xffffffffu, tq[i], off);
            }
        }
        if (lane < 4) {
#pragma unroll
            for (int j = 0; j < 4; j++)
#pragma unroll
                for (int q = 0; q < 2; q++) {
                    ssum[w][j * 8 + 2 * lane + q] = ts[j * 2 + q];
                    ssq[w][j * 8 + 2 * lane + q]  = tq[j * 2 + q];
                }
        }
        __syncthreads();
        if (tid < 128) {
            int g = tid >> 5, c = tid & 31;
            float s = ssum[g][c] + ssum[g + 4][c];
            float q = ssq[g][c] + ssq[g + 4][c];
            int col = d0 + g * 32 + c;
            g_p2s[col * 128 + y + t2 * 64] = s;
            g_p2q[col * 128 + y + t2 * 64] = q;
        }
        __syncthreads();
    }

    // grid barrier + BN2 finalize by last block
    __threadfence();
    __syncthreads();
    if (tid == 0) {
        int old = atomicAdd(&g_cntC, 1);
        islast = (old == 255);
    }
    __syncthreads();
    if (islast) {
        __threadfence();
#pragma unroll
        for (int cc = 0; cc < 2; cc++) {
            int col = tid + cc * 256;
            const float4* p4s = reinterpret_cast<const float4*>(&g_p2s[col * 128]);
            const float4* p4q = reinterpret_cast<const float4*>(&g_p2q[col * 128]);
            float s = 0.f, q = 0.f;
#pragma unroll 8
            for (int r = 0; r < 32; r++) {
                float4 a = p4s[r];
                float4 b = p4q[r];
                s += a.x + a.y + a.z + a.w;
                q += b.x + b.y + b.z + b.w;
            }
            float inv = 1.f / (float)CNT2;
            float mu = s * inv;
            float var = q * inv - mu * mu;
            float sc = gamma2[col] * rsqrtf(var + EPS);
            g_bn2[col] = sc;
            g_bn2[512 + col] = beta2[col] - mu * sc;
        }
        __threadfence();
        __syncthreads();
        if (tid == 0) atomicExch(&g_flagC, 1);
    }
    if (tid == 0) {
        while (atomicAdd(&g_flagC, 0) == 0) __nanosleep(64);
    }
    __syncthreads();
    __threadfence();

    // apply BN2 affine + leaky from registers, store final out
    float scv[4][2], biv[4][2];
#pragma unroll
    for (int j = 0; j < 4; j++) {
        int col = d0 + n_base + j * 8 + 2 * tig;
        scv[j][0] = g_bn2[col];
        scv[j][1] = g_bn2[col + 1];
        biv[j][0] = g_bn2[512 + col];
        biv[j][1] = g_bn2[513 + col];
    }
#pragma unroll
    for (int t2 = 0; t2 < 2; t2++) {
        int p0 = (y + t2 * 64) * 64;
#pragma unroll
        for (int r = 0; r < 2; r++) {
            int prow = p0 + m_base + r * 16 + grp;
#pragma unroll
            for (int j = 0; j < 4; j++) {
                int col = d0 + n_base + j * 8 + 2 * tig;
                float v0 = scv[j][0] * acc[t2][r][j][0] + biv[j][0];
                float v1 = scv[j][1] * acc[t2][r][j][1] + biv[j][1];
                float v2 = scv[j][0] * acc[t2][r][j][2] + biv[j][0];
                float v3 = scv[j][1] * acc[t2][r][j][3] + biv[j][1];
                v0 = fmaxf(v0, 0.2f * v0);
                v1 = fmaxf(v1, 0.2f * v1);
                v2 = fmaxf(v2, 0.2f * v2);
                v3 = fmaxf(v3, 0.2f * v3);
                *reinterpret_cast<float2*>(&out[prow * 512 + col]) = make_float2(v0, v1);
                *reinterpret_cast<float2*>(&out[(prow + 8) * 512 + col]) = make_float2(v2, v3);
            }
        }
    }

    __threadfence();
    __syncthreads();
    if (tid == 0) {
        int old = atomicAdd(&g_cntD, 1);
        if (old == 255) {
            g_cntC = 0;
            g_cntD = 0;
            g_flagC = 0;
        }
    }
}

// ---------------------------------------------------------------------------
extern "C" void kernel_launch(void* const* d_in, const int* in_sizes, int n_in,
                              void* d_out, int out_size) {
    const float* x      = (const float*)d_in[0];
    const int*   idx    = (const int*)  d_in[1];
    const float* W1     = (const float*)d_in[2];
    const float* gamma1 = (const float*)d_in[3];
    const float* beta1  = (const float*)d_in[4];
    const float* W2     = (const float*)d_in[5];
    const float* gamma2 = (const float*)d_in[6];
    const float* beta2  = (const float*)d_in[7];
    float* out = (float*)d_out;

    k0_prepw<<<192, 256>>>(W1, W2);
    kA_gemm1<<<128, 512>>>(x);
    kB_gather<<<256, 256>>>(idx, gamma1, beta1);
    kC_gemm2<<<dim3(4, 64), 256>>>(gamma2, beta2, out);
}